// round 2
// baseline (speedup 1.0000x reference)
#include <cuda_runtime.h>
#include <math.h>

// Problem constants
#define Bq 8
#define Nq 1025
#define Cq 3200
#define Hq 25
#define Dq 128
#define Mq (Bq * Nq)        // 8200
#define QKV_N (3 * Cq)      // 9600
#define EPSq 1e-6f

// Scratch (alloc-free rule: __device__ globals)
__device__ float g_qkv[(size_t)Mq * QKV_N];   // 315 MB
__device__ float g_att[(size_t)Mq * Cq];      // 105 MB

// ---------------------------------------------------------------------------
// SGEMM: C[M,N] = A[M,K] @ B[K,N] + bias[N]
// 128x128 tile, BK=8, 256 threads, 8x8 per thread. N % 128 == 0, K % 8 == 0.
// ---------------------------------------------------------------------------
__global__ __launch_bounds__(256) void sgemm_bias(
    const float* __restrict__ A, const float* __restrict__ Bm,
    const float* __restrict__ bias, float* __restrict__ C,
    int M, int N, int K)
{
    __shared__ float As[8][128];
    __shared__ float Bs[8][128];

    const int tid = threadIdx.x;
    const int m0 = blockIdx.y * 128;
    const int n0 = blockIdx.x * 128;
    const int ty = tid / 16, tx = tid % 16;

    const int aRow  = tid >> 1;          // 0..127
    const int aCol4 = (tid & 1) * 4;     // 0 or 4
    const int bRow  = tid >> 5;          // 0..7
    const int bCol4 = (tid & 31) * 4;    // 0..124

    float acc[8][8];
    #pragma unroll
    for (int i = 0; i < 8; i++)
        #pragma unroll
        for (int j = 0; j < 8; j++) acc[i][j] = 0.f;

    for (int k0 = 0; k0 < K; k0 += 8) {
        float4 av = make_float4(0.f, 0.f, 0.f, 0.f);
        if (m0 + aRow < M)
            av = *(const float4*)(A + (size_t)(m0 + aRow) * K + k0 + aCol4);
        As[aCol4 + 0][aRow] = av.x;
        As[aCol4 + 1][aRow] = av.y;
        As[aCol4 + 2][aRow] = av.z;
        As[aCol4 + 3][aRow] = av.w;

        float4 bv = *(const float4*)(Bm + (size_t)(k0 + bRow) * N + n0 + bCol4);
        *(float4*)&Bs[bRow][bCol4] = bv;

        __syncthreads();

        #pragma unroll
        for (int k = 0; k < 8; k++) {
            float ra[8], rb[8];
            #pragma unroll
            for (int i = 0; i < 8; i++) ra[i] = As[k][ty * 8 + i];
            #pragma unroll
            for (int j = 0; j < 8; j++) rb[j] = Bs[k][tx * 8 + j];
            #pragma unroll
            for (int i = 0; i < 8; i++)
                #pragma unroll
                for (int j = 0; j < 8; j++)
                    acc[i][j] += ra[i] * rb[j];
        }
        __syncthreads();
    }

    #pragma unroll
    for (int i = 0; i < 8; i++) {
        int m = m0 + ty * 8 + i;
        if (m < M) {
            #pragma unroll
            for (int j = 0; j < 8; j += 4) {
                int n = n0 + tx * 8 + j;
                float4 o;
                o.x = acc[i][j + 0] + bias[n + 0];
                o.y = acc[i][j + 1] + bias[n + 1];
                o.z = acc[i][j + 2] + bias[n + 2];
                o.w = acc[i][j + 3] + bias[n + 3];
                *(float4*)(C + (size_t)m * N + n) = o;
            }
        }
    }
}

// ---------------------------------------------------------------------------
// RMSNorm in-place over q / k slices of g_qkv. One block per (row, which).
// ---------------------------------------------------------------------------
__global__ __launch_bounds__(256) void rmsnorm_kernel(
    float* __restrict__ qkv, const float* __restrict__ qw,
    const float* __restrict__ kw)
{
    const int row = blockIdx.x;
    const int which = blockIdx.y;            // 0=q, 1=k
    const float* w = which ? kw : qw;
    float* p = qkv + (size_t)row * QKV_N + which * Cq;

    float ss = 0.f;
    for (int c = threadIdx.x * 4; c < Cq; c += 256 * 4) {
        float4 v = *(const float4*)(p + c);
        ss += v.x * v.x + v.y * v.y + v.z * v.z + v.w * v.w;
    }
    #pragma unroll
    for (int o = 16; o; o >>= 1) ss += __shfl_xor_sync(0xffffffffu, ss, o);

    __shared__ float red[8];
    if ((threadIdx.x & 31) == 0) red[threadIdx.x >> 5] = ss;
    __syncthreads();
    if (threadIdx.x < 8) {
        float v = red[threadIdx.x];
        #pragma unroll
        for (int o = 4; o; o >>= 1) v += __shfl_xor_sync(0xffu, v, o);
        if (threadIdx.x == 0) red[0] = v;
    }
    __syncthreads();

    const float inv = rsqrtf(red[0] * (1.f / Cq) + EPSq);
    for (int c = threadIdx.x * 4; c < Cq; c += 256 * 4) {
        float4 v = *(const float4*)(p + c);
        float4 wv = *(const float4*)(w + c);
        v.x *= inv * wv.x; v.y *= inv * wv.y;
        v.z *= inv * wv.z; v.w *= inv * wv.w;
        *(float4*)(p + c) = v;
    }
}

// ---------------------------------------------------------------------------
// Flash attention: one block per (q_tile=64, head, batch). D=128 fixed.
// Online softmax, O in registers (4 rows x 8 cols per thread, 256 threads).
// ---------------------------------------------------------------------------
#define FA_QS_STRIDE 132
#define FA_KT_STRIDE 68
#define FA_VS_STRIDE 132
#define FA_PS_STRIDE 68
#define FA_SMEM_FLOATS (64*FA_QS_STRIDE + 128*FA_KT_STRIDE + 64*FA_VS_STRIDE + 64*FA_PS_STRIDE + 3*64)
#define FA_SMEM_BYTES (FA_SMEM_FLOATS * 4)

__global__ __launch_bounds__(256) void flash_attn(
    const float* __restrict__ qkv, float* __restrict__ out)
{
    extern __shared__ float sm[];
    float* Qs   = sm;
    float* Kts  = Qs  + 64 * FA_QS_STRIDE;
    float* Vs   = Kts + 128 * FA_KT_STRIDE;
    float* Ps   = Vs  + 64 * FA_VS_STRIDE;
    float* m_s  = Ps  + 64 * FA_PS_STRIDE;
    float* l_s  = m_s + 64;
    float* corr = l_s + 64;

    const int qt = blockIdx.x;
    const int h  = blockIdx.y;
    const int b  = blockIdx.z;
    const int tid = threadIdx.x;
    const int ty = tid / 16, tx = tid % 16;
    const float scale = 0.08838834764831845f;  // 128^-0.5

    const int q0 = qt * 64;
    const float* qbase = qkv + (size_t)b * Nq * QKV_N + h * Dq;
    const float* kbase = qbase + Cq;
    const float* vbase = qbase + 2 * Cq;

    // Load Q tile (pre-scaled)
    for (int idx = tid; idx < 64 * 32; idx += 256) {
        int r = idx >> 5, c4 = (idx & 31) * 4;
        int n = q0 + r;
        float4 v = make_float4(0.f, 0.f, 0.f, 0.f);
        if (n < Nq) v = *(const float4*)(qbase + (size_t)n * QKV_N + c4);
        Qs[r * FA_QS_STRIDE + c4 + 0] = v.x * scale;
        Qs[r * FA_QS_STRIDE + c4 + 1] = v.y * scale;
        Qs[r * FA_QS_STRIDE + c4 + 2] = v.z * scale;
        Qs[r * FA_QS_STRIDE + c4 + 3] = v.w * scale;
    }
    if (tid < 64) { m_s[tid] = -1e30f; l_s[tid] = 0.f; }

    float o[4][8];
    #pragma unroll
    for (int i = 0; i < 4; i++)
        #pragma unroll
        for (int c = 0; c < 8; c++) o[i][c] = 0.f;

    __syncthreads();

    for (int kt = 0; kt < 17; kt++) {
        const int k0g = kt * 64;

        // Load K (transposed) and V tiles
        for (int idx = tid; idx < 64 * 32; idx += 256) {
            int r = idx >> 5, c4 = (idx & 31) * 4;
            int n = k0g + r;
            float4 kv = make_float4(0.f, 0.f, 0.f, 0.f);
            float4 vv = make_float4(0.f, 0.f, 0.f, 0.f);
            if (n < Nq) {
                kv = *(const float4*)(kbase + (size_t)n * QKV_N + c4);
                vv = *(const float4*)(vbase + (size_t)n * QKV_N + c4);
            }
            Kts[(c4 + 0) * FA_KT_STRIDE + r] = kv.x;
            Kts[(c4 + 1) * FA_KT_STRIDE + r] = kv.y;
            Kts[(c4 + 2) * FA_KT_STRIDE + r] = kv.z;
            Kts[(c4 + 3) * FA_KT_STRIDE + r] = kv.w;
            *(float4*)&Vs[r * FA_VS_STRIDE + c4] = vv;
        }
        __syncthreads();

        // S = Q K^T  (4x4 per thread)
        float s[4][4];
        #pragma unroll
        for (int i = 0; i < 4; i++)
            #pragma unroll
            for (int j = 0; j < 4; j++) s[i][j] = 0.f;

        #pragma unroll 4
        for (int d = 0; d < 128; d++) {
            float qf[4], kf[4];
            #pragma unroll
            for (int i = 0; i < 4; i++) qf[i] = Qs[(ty * 4 + i) * FA_QS_STRIDE + d];
            float4 kv4 = *(const float4*)&Kts[d * FA_KT_STRIDE + tx * 4];
            kf[0] = kv4.x; kf[1] = kv4.y; kf[2] = kv4.z; kf[3] = kv4.w;
            #pragma unroll
            for (int i = 0; i < 4; i++)
                #pragma unroll
                for (int j = 0; j < 4; j++)
                    s[i][j] += qf[i] * kf[j];
        }

        // Write masked S to smem
        #pragma unroll
        for (int i = 0; i < 4; i++)
            #pragma unroll
            for (int j = 0; j < 4; j++) {
                int kk = k0g + tx * 4 + j;
                Ps[(ty * 4 + i) * FA_PS_STRIDE + tx * 4 + j] =
                    (kk < Nq) ? s[i][j] : -1e30f;
            }
        __syncthreads();

        // Online softmax: 4 threads per row
        {
            const int r = tid >> 2;
            const int q4 = tid & 3;
            float mx = -1e30f;
            for (int c = q4 * 16; c < q4 * 16 + 16; c++)
                mx = fmaxf(mx, Ps[r * FA_PS_STRIDE + c]);
            mx = fmaxf(mx, __shfl_xor_sync(0xffffffffu, mx, 1));
            mx = fmaxf(mx, __shfl_xor_sync(0xffffffffu, mx, 2));
            const float mold = m_s[r];
            const float mnew = fmaxf(mold, mx);
            float sum = 0.f;
            for (int c = q4 * 16; c < q4 * 16 + 16; c++) {
                float pv = __expf(Ps[r * FA_PS_STRIDE + c] - mnew);
                Ps[r * FA_PS_STRIDE + c] = pv;
                sum += pv;
            }
            sum += __shfl_xor_sync(0xffffffffu, sum, 1);
            sum += __shfl_xor_sync(0xffffffffu, sum, 2);
            if (q4 == 0) {
                float cr = __expf(mold - mnew);
                l_s[r] = l_s[r] * cr + sum;
                m_s[r] = mnew;
                corr[r] = cr;
            }
        }
        __syncthreads();

        // O = O*corr + P V  (4 rows x 8 cols per thread)
        {
            float cr[4];
            #pragma unroll
            for (int i = 0; i < 4; i++) cr[i] = corr[ty * 4 + i];
            #pragma unroll
            for (int i = 0; i < 4; i++)
                #pragma unroll
                for (int c = 0; c < 8; c++) o[i][c] *= cr[i];

            #pragma unroll 4
            for (int kr = 0; kr < 64; kr++) {
                float pf[4];
                #pragma unroll
                for (int i = 0; i < 4; i++)
                    pf[i] = Ps[(ty * 4 + i) * FA_PS_STRIDE + kr];
                float4 v0 = *(const float4*)&Vs[kr * FA_VS_STRIDE + tx * 8];
                float4 v1 = *(const float4*)&Vs[kr * FA_VS_STRIDE + tx * 8 + 4];
                float vf[8] = {v0.x, v0.y, v0.z, v0.w, v1.x, v1.y, v1.z, v1.w};
                #pragma unroll
                for (int i = 0; i < 4; i++)
                    #pragma unroll
                    for (int c = 0; c < 8; c++)
                        o[i][c] += pf[i] * vf[c];
            }
        }
        __syncthreads();
    }

    // Write normalized output
    #pragma unroll
    for (int i = 0; i < 4; i++) {
        int n = q0 + ty * 4 + i;
        if (n < Nq) {
            float invl = 1.f / l_s[ty * 4 + i];
            float* op = out + ((size_t)(b * Nq + n)) * Cq + h * Dq + tx * 8;
            #pragma unroll
            for (int c = 0; c < 8; c++) op[c] = o[i][c] * invl;
        }
    }
}

// ---------------------------------------------------------------------------
extern "C" void kernel_launch(void* const* d_in, const int* in_sizes, int n_in,
                              void* d_out, int out_size)
{
    const float* x        = (const float*)d_in[0];
    const float* qkv_w    = (const float*)d_in[1];
    const float* qkv_b    = (const float*)d_in[2];
    const float* q_norm_w = (const float*)d_in[3];
    const float* k_norm_w = (const float*)d_in[4];
    const float* proj_w   = (const float*)d_in[5];
    const float* proj_b   = (const float*)d_in[6];
    float* out = (float*)d_out;

    float* qkvp = nullptr;
    float* attp = nullptr;
    cudaGetSymbolAddress((void**)&qkvp, g_qkv);
    cudaGetSymbolAddress((void**)&attp, g_att);

    // 1) qkv = x @ qkv_w + qkv_b
    sgemm_bias<<<dim3(QKV_N / 128, (Mq + 127) / 128), 256>>>(
        x, qkv_w, qkv_b, qkvp, Mq, QKV_N, Cq);

    // 2) RMSNorm on q and k slices (in place)
    rmsnorm_kernel<<<dim3(Mq, 2), 256>>>(qkvp, q_norm_w, k_norm_w);

    // 3) Flash attention -> g_att
    cudaFuncSetAttribute(flash_attn,
                         cudaFuncAttributeMaxDynamicSharedMemorySize,
                         FA_SMEM_BYTES);
    flash_attn<<<dim3(17, Hq, Bq), 256, FA_SMEM_BYTES>>>(qkvp, attp);

    // 4) out = g_att @ proj_w + proj_b
    sgemm_bias<<<dim3(Cq / 128, (Mq + 127) / 128), 256>>>(
        attp, proj_w, proj_b, out, Mq, Cq, Cq);
}

// round 4
// speedup vs baseline: 2.1706x; 2.1706x over previous
#include <cuda_runtime.h>
#include <cuda_bf16.h>
#include <cstdint>
#include <math.h>

// Problem constants
#define Bq 8
#define Nq 1025
#define Cq 3200
#define Hq 25
#define Dq 128
#define Mq (Bq * Nq)        // 8200
#define QKV_N (3 * Cq)      // 9600
#define Kp 9600             // K' = 3*Cq (split-tripled K)
#define EPSq 1e-6f

// Scratch (__device__ globals per alloc-free rule)
__device__ float g_qkv[(size_t)Mq * QKV_N];
__device__ float g_att[(size_t)Mq * Cq];
__device__ __nv_bfloat16 g_as[(size_t)Mq * Kp];
__device__ __nv_bfloat16 g_wq[(size_t)QKV_N * Kp];
__device__ __nv_bfloat16 g_wp[(size_t)Cq * Kp];

// ===========================================================================
// helpers
// ===========================================================================
__device__ __forceinline__ uint32_t smem_u32(const void* p) {
    uint32_t a;
    asm("{ .reg .u64 t; cvta.to.shared.u64 t, %1; cvt.u32.u64 %0, t; }"
        : "=r"(a) : "l"(p));
    return a;
}
__device__ __forceinline__ uint32_t swz128(uint32_t off) {
    return off ^ ((off >> 3) & 0x70);
}
__device__ __forceinline__ void cp16(uint32_t s, const void* g) {
    asm volatile("cp.async.cg.shared.global [%0], [%1], 16;"
                 :: "r"(s), "l"(g) : "memory");
}
#define CP_COMMIT() asm volatile("cp.async.commit_group;" ::: "memory")

#define LDSM_X4(r, addr)                                                       \
    asm volatile("ldmatrix.sync.aligned.m8n8.x4.shared.b16 {%0,%1,%2,%3}, [%4];" \
        : "=r"((r)[0]), "=r"((r)[1]), "=r"((r)[2]), "=r"((r)[3]) : "r"(addr))

#define MMA16816(d, a, b)                                                      \
    asm volatile("mma.sync.aligned.m16n8k16.row.col.f32.bf16.bf16.f32 "        \
        "{%0,%1,%2,%3}, {%4,%5,%6,%7}, {%8,%9}, {%0,%1,%2,%3};"                \
        : "+f"((d)[0]), "+f"((d)[1]), "+f"((d)[2]), "+f"((d)[3])               \
        : "r"((a)[0]), "r"((a)[1]), "r"((a)[2]), "r"((a)[3]),                  \
          "r"((b)[0]), "r"((b)[1]))

// ===========================================================================
// Split kernels: fp32 -> bf16 hi/lo with K tripled
// A' = [hi | hi | lo],  W'^T row n = [hi | lo | hi]
// ===========================================================================
__global__ __launch_bounds__(256) void split_a_kernel(
    const float* __restrict__ in, __nv_bfloat16* __restrict__ out, int M)
{
    size_t idx = (size_t)blockIdx.x * 256 + threadIdx.x;
    if (idx * 2 >= (size_t)M * Cq) return;
    int m = (int)((idx * 2) / Cq);
    int k = (int)((idx * 2) % Cq);
    float2 v = *(const float2*)(in + (size_t)m * Cq + k);
    __nv_bfloat16 h0 = __float2bfloat16_rn(v.x);
    __nv_bfloat16 h1 = __float2bfloat16_rn(v.y);
    __nv_bfloat16 l0 = __float2bfloat16_rn(v.x - __bfloat162float(h0));
    __nv_bfloat16 l1 = __float2bfloat16_rn(v.y - __bfloat162float(h1));
    __nv_bfloat162 hh; hh.x = h0; hh.y = h1;
    __nv_bfloat162 ll; ll.x = l0; ll.y = l1;
    __nv_bfloat16* row = out + (size_t)m * Kp;
    *(__nv_bfloat162*)(row + k)          = hh;
    *(__nv_bfloat162*)(row + Cq + k)     = hh;
    *(__nv_bfloat162*)(row + 2 * Cq + k) = ll;
}

__global__ __launch_bounds__(256) void split_wt_kernel(
    const float* __restrict__ W, __nv_bfloat16* __restrict__ out, int Nw)
{
    __shared__ float tile[32][33];
    int n0 = blockIdx.x * 32, k0 = blockIdx.y * 32;
    int tx = threadIdx.x, ty = threadIdx.y;       // 32 x 8
    #pragma unroll
    for (int i = ty; i < 32; i += 8)
        tile[i][tx] = W[(size_t)(k0 + i) * Nw + n0 + tx];
    __syncthreads();
    #pragma unroll
    for (int i = ty; i < 32; i += 8) {
        int n = n0 + i, k = k0 + tx;
        float v = tile[tx][i];
        __nv_bfloat16 h = __float2bfloat16_rn(v);
        __nv_bfloat16 l = __float2bfloat16_rn(v - __bfloat162float(h));
        __nv_bfloat16* row = out + (size_t)n * Kp;
        row[k]          = h;
        row[Cq + k]     = l;
        row[2 * Cq + k] = h;
    }
}

// ===========================================================================
// bf16 mma.sync GEMM: C[M,Nt] = A'[M,Kp] @ Bt'[Nt,Kp]^T + bias
// CTA 128x128x64, 8 warps (2x4), warp tile 64x32, cp.async double buffer.
// ===========================================================================
#define GBM 128
#define GBN 128
#define GBK 64
#define GNIT (Kp / GBK)            // 150
#define ABYTES (GBM * GBK * 2)     // 16 KB
#define BBYTES (GBN * GBK * 2)     // 16 KB
#define BUFB (ABYTES + BBYTES)     // 32 KB
#define GSMEM_TOTAL (2 * BUFB)     // 64 KB
#define G_GM 8

__global__ __launch_bounds__(256, 2) void gemm_mma(
    const __nv_bfloat16* __restrict__ A,
    const __nv_bfloat16* __restrict__ Bt,
    const float* __restrict__ bias,
    float* __restrict__ C,
    int M, int Nt, int mt, int nt)
{
    extern __shared__ char smem[];
    const uint32_t sbase = smem_u32(smem);
    const int tid = threadIdx.x;
    const int wid = tid >> 5, lane = tid & 31;
    const int wm = wid >> 2, wn = wid & 3;     // 2 x 4 warp grid

    // grouped tile mapping: G_GM m-tiles per group, m fastest inside group
    int bid = blockIdx.x;
    int per_group = G_GM * nt;
    int gid = bid / per_group;
    int first_m = gid * G_GM;
    int gsz = min(G_GM, mt - first_m);
    int rem = bid % per_group;
    const int m0 = (first_m + rem % gsz) * GBM;
    const int n0 = (rem / gsz) * GBN;

    float acc[4][4][4];
    #pragma unroll
    for (int i = 0; i < 4; i++)
        #pragma unroll
        for (int j = 0; j < 4; j++)
            #pragma unroll
            for (int r = 0; r < 4; r++) acc[i][j][r] = 0.f;

    // -------- tile loader (cp.async) --------
    auto load_tile = [&](int it, int buf) {
        const int k0 = it * GBK;
        const uint32_t sA = sbase + buf * BUFB;
        const uint32_t sB = sA + ABYTES;
        #pragma unroll
        for (int p = 0; p < 4; p++) {
            int id = p * 256 + tid;
            int row = id >> 3, ch = id & 7;
            uint32_t so = swz128((uint32_t)(row * 128 + ch * 16));
            int m = min(m0 + row, M - 1);      // clamp (tail tile)
            cp16(sA + so, A  + (size_t)m * Kp + k0 + ch * 8);
            cp16(sB + so, Bt + (size_t)(n0 + row) * Kp + k0 + ch * 8);
        }
        CP_COMMIT();
    };

    // -------- compute one buffered tile --------
    auto compute = [&](int buf) {
        const uint32_t sA = sbase + buf * BUFB + (uint32_t)(wm * 64 * 128);
        const uint32_t sB = sbase + buf * BUFB + ABYTES + (uint32_t)(wn * 32 * 128);
        #pragma unroll
        for (int kk = 0; kk < 4; kk++) {
            uint32_t afr[4][4];
            #pragma unroll
            for (int mi = 0; mi < 4; mi++) {
                int row = mi * 16 + (lane & 15);
                int cb = kk * 32 + ((lane >> 4) << 4);
                LDSM_X4(afr[mi], sA + swz128((uint32_t)(row * 128 + cb)));
            }
            uint32_t bfr[4][2];
            #pragma unroll
            for (int bj = 0; bj < 2; bj++) {
                int row = bj * 16 + ((lane >> 4) << 3) + (lane & 7);
                int cb = kk * 32 + (((lane >> 3) & 1) << 4);
                uint32_t r[4];
                LDSM_X4(r, sB + swz128((uint32_t)(row * 128 + cb)));
                bfr[2 * bj][0] = r[0];     bfr[2 * bj][1] = r[1];
                bfr[2 * bj + 1][0] = r[2]; bfr[2 * bj + 1][1] = r[3];
            }
            #pragma unroll
            for (int mi = 0; mi < 4; mi++)
                #pragma unroll
                for (int nj = 0; nj < 4; nj++)
                    MMA16816(acc[mi][nj], afr[mi], bfr[nj]);
        }
    };

    load_tile(0, 0);
    for (int it = 0; it < GNIT; it++) {
        if (it + 1 < GNIT) {
            load_tile(it + 1, (it + 1) & 1);
            asm volatile("cp.async.wait_group 1;" ::: "memory");
        } else {
            asm volatile("cp.async.wait_group 0;" ::: "memory");
        }
        __syncthreads();
        compute(it & 1);
        __syncthreads();
    }

    // -------- epilogue: direct fp32 stores + bias --------
    const int mbase = m0 + wm * 64;
    const int nbase = n0 + wn * 32;
    #pragma unroll
    for (int mi = 0; mi < 4; mi++) {
        #pragma unroll
        for (int nj = 0; nj < 4; nj++) {
            int r0 = mbase + mi * 16 + (lane >> 2);
            int c = nbase + nj * 8 + 2 * (lane & 3);
            float bx = bias[c], by = bias[c + 1];
            if (r0 < M) {
                float2 o = make_float2(acc[mi][nj][0] + bx, acc[mi][nj][1] + by);
                *(float2*)(C + (size_t)r0 * Nt + c) = o;
            }
            if (r0 + 8 < M) {
                float2 o = make_float2(acc[mi][nj][2] + bx, acc[mi][nj][3] + by);
                *(float2*)(C + (size_t)(r0 + 8) * Nt + c) = o;
            }
        }
    }
}

// ===========================================================================
// RMSNorm in-place over q / k slices of g_qkv.
// ===========================================================================
__global__ __launch_bounds__(256) void rmsnorm_kernel(
    float* __restrict__ qkv, const float* __restrict__ qw,
    const float* __restrict__ kw)
{
    const int row = blockIdx.x;
    const int which = blockIdx.y;
    const float* w = which ? kw : qw;
    float* p = qkv + (size_t)row * QKV_N + which * Cq;

    float ss = 0.f;
    for (int c = threadIdx.x * 4; c < Cq; c += 256 * 4) {
        float4 v = *(const float4*)(p + c);
        ss += v.x * v.x + v.y * v.y + v.z * v.z + v.w * v.w;
    }
    #pragma unroll
    for (int o = 16; o; o >>= 1) ss += __shfl_xor_sync(0xffffffffu, ss, o);
    __shared__ float red[8];
    if ((threadIdx.x & 31) == 0) red[threadIdx.x >> 5] = ss;
    __syncthreads();
    if (threadIdx.x < 8) {
        float v = red[threadIdx.x];
        #pragma unroll
        for (int o = 4; o; o >>= 1) v += __shfl_xor_sync(0xffu, v, o);
        if (threadIdx.x == 0) red[0] = v;
    }
    __syncthreads();
    const float inv = rsqrtf(red[0] * (1.f / Cq) + EPSq);
    for (int c = threadIdx.x * 4; c < Cq; c += 256 * 4) {
        float4 v = *(const float4*)(p + c);
        float4 wv = *(const float4*)(w + c);
        v.x *= inv * wv.x; v.y *= inv * wv.y;
        v.z *= inv * wv.z; v.w *= inv * wv.w;
        *(float4*)(p + c) = v;
    }
}

// ===========================================================================
// Flash attention (fp32), unchanged from passing round
// ===========================================================================
#define FA_QS_STRIDE 132
#define FA_KT_STRIDE 68
#define FA_VS_STRIDE 132
#define FA_PS_STRIDE 68
#define FA_SMEM_FLOATS (64*FA_QS_STRIDE + 128*FA_KT_STRIDE + 64*FA_VS_STRIDE + 64*FA_PS_STRIDE + 3*64)
#define FA_SMEM_BYTES (FA_SMEM_FLOATS * 4)

__global__ __launch_bounds__(256) void flash_attn(
    const float* __restrict__ qkv, float* __restrict__ out)
{
    extern __shared__ float sm[];
    float* Qs   = sm;
    float* Kts  = Qs  + 64 * FA_QS_STRIDE;
    float* Vs   = Kts + 128 * FA_KT_STRIDE;
    float* Ps   = Vs  + 64 * FA_VS_STRIDE;
    float* m_s  = Ps  + 64 * FA_PS_STRIDE;
    float* l_s  = m_s + 64;
    float* corr = l_s + 64;

    const int qt = blockIdx.x;
    const int h  = blockIdx.y;
    const int b  = blockIdx.z;
    const int tid = threadIdx.x;
    const int ty = tid / 16, tx = tid % 16;
    const float scale = 0.08838834764831845f;

    const int q0 = qt * 64;
    const float* qbase = qkv + (size_t)b * Nq * QKV_N + h * Dq;
    const float* kbase = qbase + Cq;
    const float* vbase = qbase + 2 * Cq;

    for (int idx = tid; idx < 64 * 32; idx += 256) {
        int r = idx >> 5, c4 = (idx & 31) * 4;
        int n = q0 + r;
        float4 v = make_float4(0.f, 0.f, 0.f, 0.f);
        if (n < Nq) v = *(const float4*)(qbase + (size_t)n * QKV_N + c4);
        Qs[r * FA_QS_STRIDE + c4 + 0] = v.x * scale;
        Qs[r * FA_QS_STRIDE + c4 + 1] = v.y * scale;
        Qs[r * FA_QS_STRIDE + c4 + 2] = v.z * scale;
        Qs[r * FA_QS_STRIDE + c4 + 3] = v.w * scale;
    }
    if (tid < 64) { m_s[tid] = -1e30f; l_s[tid] = 0.f; }

    float o[4][8];
    #pragma unroll
    for (int i = 0; i < 4; i++)
        #pragma unroll
        for (int c = 0; c < 8; c++) o[i][c] = 0.f;
    __syncthreads();

    for (int kt = 0; kt < 17; kt++) {
        const int k0g = kt * 64;
        for (int idx = tid; idx < 64 * 32; idx += 256) {
            int r = idx >> 5, c4 = (idx & 31) * 4;
            int n = k0g + r;
            float4 kv = make_float4(0.f, 0.f, 0.f, 0.f);
            float4 vv = make_float4(0.f, 0.f, 0.f, 0.f);
            if (n < Nq) {
                kv = *(const float4*)(kbase + (size_t)n * QKV_N + c4);
                vv = *(const float4*)(vbase + (size_t)n * QKV_N + c4);
            }
            Kts[(c4 + 0) * FA_KT_STRIDE + r] = kv.x;
            Kts[(c4 + 1) * FA_KT_STRIDE + r] = kv.y;
            Kts[(c4 + 2) * FA_KT_STRIDE + r] = kv.z;
            Kts[(c4 + 3) * FA_KT_STRIDE + r] = kv.w;
            *(float4*)&Vs[r * FA_VS_STRIDE + c4] = vv;
        }
        __syncthreads();

        float s[4][4];
        #pragma unroll
        for (int i = 0; i < 4; i++)
            #pragma unroll
            for (int j = 0; j < 4; j++) s[i][j] = 0.f;

        #pragma unroll 4
        for (int d = 0; d < 128; d++) {
            float qf[4], kf[4];
            #pragma unroll
            for (int i = 0; i < 4; i++) qf[i] = Qs[(ty * 4 + i) * FA_QS_STRIDE + d];
            float4 kv4 = *(const float4*)&Kts[d * FA_KT_STRIDE + tx * 4];
            kf[0] = kv4.x; kf[1] = kv4.y; kf[2] = kv4.z; kf[3] = kv4.w;
            #pragma unroll
            for (int i = 0; i < 4; i++)
                #pragma unroll
                for (int j = 0; j < 4; j++)
                    s[i][j] += qf[i] * kf[j];
        }

        #pragma unroll
        for (int i = 0; i < 4; i++)
            #pragma unroll
            for (int j = 0; j < 4; j++) {
                int kk = k0g + tx * 4 + j;
                Ps[(ty * 4 + i) * FA_PS_STRIDE + tx * 4 + j] =
                    (kk < Nq) ? s[i][j] : -1e30f;
            }
        __syncthreads();

        {
            const int r = tid >> 2;
            const int q4 = tid & 3;
            float mx = -1e30f;
            for (int c = q4 * 16; c < q4 * 16 + 16; c++)
                mx = fmaxf(mx, Ps[r * FA_PS_STRIDE + c]);
            mx = fmaxf(mx, __shfl_xor_sync(0xffffffffu, mx, 1));
            mx = fmaxf(mx, __shfl_xor_sync(0xffffffffu, mx, 2));
            const float mold = m_s[r];
            const float mnew = fmaxf(mold, mx);
            float sum = 0.f;
            for (int c = q4 * 16; c < q4 * 16 + 16; c++) {
                float pv = __expf(Ps[r * FA_PS_STRIDE + c] - mnew);
                Ps[r * FA_PS_STRIDE + c] = pv;
                sum += pv;
            }
            sum += __shfl_xor_sync(0xffffffffu, sum, 1);
            sum += __shfl_xor_sync(0xffffffffu, sum, 2);
            if (q4 == 0) {
                float cr = __expf(mold - mnew);
                l_s[r] = l_s[r] * cr + sum;
                m_s[r] = mnew;
                corr[r] = cr;
            }
        }
        __syncthreads();

        {
            float cr[4];
            #pragma unroll
            for (int i = 0; i < 4; i++) cr[i] = corr[ty * 4 + i];
            #pragma unroll
            for (int i = 0; i < 4; i++)
                #pragma unroll
                for (int c = 0; c < 8; c++) o[i][c] *= cr[i];

            #pragma unroll 4
            for (int kr = 0; kr < 64; kr++) {
                float pf[4];
                #pragma unroll
                for (int i = 0; i < 4; i++)
                    pf[i] = Ps[(ty * 4 + i) * FA_PS_STRIDE + kr];
                float4 v0 = *(const float4*)&Vs[kr * FA_VS_STRIDE + tx * 8];
                float4 v1 = *(const float4*)&Vs[kr * FA_VS_STRIDE + tx * 8 + 4];
                float vf[8] = {v0.x, v0.y, v0.z, v0.w, v1.x, v1.y, v1.z, v1.w};
                #pragma unroll
                for (int i = 0; i < 4; i++)
                    #pragma unroll
                    for (int c = 0; c < 8; c++)
                        o[i][c] += pf[i] * vf[c];
            }
        }
        __syncthreads();
    }

    #pragma unroll
    for (int i = 0; i < 4; i++) {
        int n = q0 + ty * 4 + i;
        if (n < Nq) {
            float invl = 1.f / l_s[ty * 4 + i];
            float* op = out + ((size_t)(b * Nq + n)) * Cq + h * Dq + tx * 8;
            #pragma unroll
            for (int c = 0; c < 8; c++) op[c] = o[i][c] * invl;
        }
    }
}

// ===========================================================================
extern "C" void kernel_launch(void* const* d_in, const int* in_sizes, int n_in,
                              void* d_out, int out_size)
{
    const float* x        = (const float*)d_in[0];
    const float* qkv_w    = (const float*)d_in[1];
    const float* qkv_b    = (const float*)d_in[2];
    const float* q_norm_w = (const float*)d_in[3];
    const float* k_norm_w = (const float*)d_in[4];
    const float* proj_w   = (const float*)d_in[5];
    const float* proj_b   = (const float*)d_in[6];
    float* out = (float*)d_out;

    float *qkvp = nullptr, *attp = nullptr;
    __nv_bfloat16 *asp = nullptr, *wqp = nullptr, *wpp = nullptr;
    cudaGetSymbolAddress((void**)&qkvp, g_qkv);
    cudaGetSymbolAddress((void**)&attp, g_att);
    cudaGetSymbolAddress((void**)&asp, g_as);
    cudaGetSymbolAddress((void**)&wqp, g_wq);
    cudaGetSymbolAddress((void**)&wpp, g_wp);

    cudaFuncSetAttribute(gemm_mma,
                         cudaFuncAttributeMaxDynamicSharedMemorySize, GSMEM_TOTAL);
    cudaFuncSetAttribute(flash_attn,
                         cudaFuncAttributeMaxDynamicSharedMemorySize, FA_SMEM_BYTES);

    const int mt = (Mq + GBM - 1) / GBM;        // 65
    const int nt_qkv = QKV_N / GBN;             // 75
    const int nt_prj = Cq / GBN;                // 25

    // 1) split inputs / weights into bf16 hi/lo (K tripled)
    {
        size_t e2 = (size_t)Mq * Cq / 2;
        split_a_kernel<<<(unsigned)((e2 + 255) / 256), 256>>>(x, asp, Mq);
    }
    split_wt_kernel<<<dim3(QKV_N / 32, Cq / 32), dim3(32, 8)>>>(qkv_w, wqp, QKV_N);
    split_wt_kernel<<<dim3(Cq / 32, Cq / 32), dim3(32, 8)>>>(proj_w, wpp, Cq);

    // 2) qkv = x @ qkv_w + b  (bf16x3 mma.sync)
    gemm_mma<<<mt * nt_qkv, 256, GSMEM_TOTAL>>>(
        asp, wqp, qkv_b, qkvp, Mq, QKV_N, mt, nt_qkv);

    // 3) RMSNorm q/k in place
    rmsnorm_kernel<<<dim3(Mq, 2), 256>>>(qkvp, q_norm_w, k_norm_w);

    // 4) attention -> g_att
    flash_attn<<<dim3(17, Hq, Bq), 256, FA_SMEM_BYTES>>>(qkvp, attp);

    // 5) split attention output
    {
        size_t e2 = (size_t)Mq * Cq / 2;
        split_a_kernel<<<(unsigned)((e2 + 255) / 256), 256>>>(attp, asp, Mq);
    }

    // 6) out = att @ proj_w + b
    gemm_mma<<<mt * nt_prj, 256, GSMEM_TOTAL>>>(
        asp, wpp, proj_b, out, Mq, Cq, mt, nt_prj);
}

// round 5
// speedup vs baseline: 2.8711x; 1.3227x over previous
#include <cuda_runtime.h>
#include <cuda_bf16.h>
#include <cstdint>
#include <math.h>

// Problem constants
#define Bq 8
#define Nq 1025
#define Cq 3200
#define Hq 25
#define Dq 128
#define Mq (Bq * Nq)        // 8200
#define QKV_N (3 * Cq)      // 9600
#define Kp 9600             // K' = 3*Cq (split-tripled K)
#define EPSq 1e-6f

// Scratch (__device__ globals per alloc-free rule)
__device__ float g_qkv[(size_t)Mq * QKV_N];
__device__ __nv_bfloat16 g_as[(size_t)Mq * Kp];
__device__ __nv_bfloat16 g_wq[(size_t)QKV_N * Kp];
__device__ __nv_bfloat16 g_wp[(size_t)Cq * Kp];

// ===========================================================================
// helpers
// ===========================================================================
__device__ __forceinline__ uint32_t smem_u32(const void* p) {
    uint32_t a;
    asm("{ .reg .u64 t; cvta.to.shared.u64 t, %1; cvt.u32.u64 %0, t; }"
        : "=r"(a) : "l"(p));
    return a;
}
__device__ __forceinline__ uint32_t swz128(uint32_t off) {
    return off ^ ((off >> 3) & 0x70);
}
__device__ __forceinline__ void cp16(uint32_t s, const void* g) {
    asm volatile("cp.async.cg.shared.global [%0], [%1], 16;"
                 :: "r"(s), "l"(g) : "memory");
}
#define CP_COMMIT() asm volatile("cp.async.commit_group;" ::: "memory")

#define LDSM_X4(r, addr)                                                       \
    asm volatile("ldmatrix.sync.aligned.m8n8.x4.shared.b16 {%0,%1,%2,%3}, [%4];" \
        : "=r"((r)[0]), "=r"((r)[1]), "=r"((r)[2]), "=r"((r)[3]) : "r"(addr))

#define LDSM_X4_T(r, addr)                                                     \
    asm volatile("ldmatrix.sync.aligned.m8n8.x4.trans.shared.b16 {%0,%1,%2,%3}, [%4];" \
        : "=r"((r)[0]), "=r"((r)[1]), "=r"((r)[2]), "=r"((r)[3]) : "r"(addr))

#define MMA16816(d, a, b)                                                      \
    asm volatile("mma.sync.aligned.m16n8k16.row.col.f32.bf16.bf16.f32 "        \
        "{%0,%1,%2,%3}, {%4,%5,%6,%7}, {%8,%9}, {%0,%1,%2,%3};"                \
        : "+f"((d)[0]), "+f"((d)[1]), "+f"((d)[2]), "+f"((d)[3])               \
        : "r"((a)[0]), "r"((a)[1]), "r"((a)[2]), "r"((a)[3]),                  \
          "r"((b)[0]), "r"((b)[1]))

// ===========================================================================
// Split kernels: fp32 -> bf16 hi/lo with K tripled
// A' = [hi | hi | lo],  W'^T row n = [hi | lo | hi]
// ===========================================================================
__global__ __launch_bounds__(256) void split_a_kernel(
    const float* __restrict__ in, __nv_bfloat16* __restrict__ out, int M)
{
    size_t idx = (size_t)blockIdx.x * 256 + threadIdx.x;
    if (idx * 2 >= (size_t)M * Cq) return;
    int m = (int)((idx * 2) / Cq);
    int k = (int)((idx * 2) % Cq);
    float2 v = *(const float2*)(in + (size_t)m * Cq + k);
    __nv_bfloat16 h0 = __float2bfloat16_rn(v.x);
    __nv_bfloat16 h1 = __float2bfloat16_rn(v.y);
    __nv_bfloat16 l0 = __float2bfloat16_rn(v.x - __bfloat162float(h0));
    __nv_bfloat16 l1 = __float2bfloat16_rn(v.y - __bfloat162float(h1));
    __nv_bfloat162 hh; hh.x = h0; hh.y = h1;
    __nv_bfloat162 ll; ll.x = l0; ll.y = l1;
    __nv_bfloat16* row = out + (size_t)m * Kp;
    *(__nv_bfloat162*)(row + k)          = hh;
    *(__nv_bfloat162*)(row + Cq + k)     = hh;
    *(__nv_bfloat162*)(row + 2 * Cq + k) = ll;
}

__global__ __launch_bounds__(256) void split_wt_kernel(
    const float* __restrict__ W, __nv_bfloat16* __restrict__ out, int Nw)
{
    __shared__ float tile[32][33];
    int n0 = blockIdx.x * 32, k0 = blockIdx.y * 32;
    int tx = threadIdx.x, ty = threadIdx.y;       // 32 x 8
    #pragma unroll
    for (int i = ty; i < 32; i += 8)
        tile[i][tx] = W[(size_t)(k0 + i) * Nw + n0 + tx];
    __syncthreads();
    #pragma unroll
    for (int i = ty; i < 32; i += 8) {
        int n = n0 + i, k = k0 + tx;
        float v = tile[tx][i];
        __nv_bfloat16 h = __float2bfloat16_rn(v);
        __nv_bfloat16 l = __float2bfloat16_rn(v - __bfloat162float(h));
        __nv_bfloat16* row = out + (size_t)n * Kp;
        row[k]          = h;
        row[Cq + k]     = l;
        row[2 * Cq + k] = h;
    }
}

// ===========================================================================
// bf16 mma.sync GEMM: C[M,Nt] = A'[M,Kp] @ Bt'[Nt,Kp]^T + bias
// CTA 128x128x64, 8 warps (2x4), warp tile 64x32, cp.async 3-stage pipeline.
// ===========================================================================
#define GBM 128
#define GBN 128
#define GBK 64
#define GNIT (Kp / GBK)            // 150
#define ABYTES (GBM * GBK * 2)     // 16 KB
#define BBYTES (GBN * GBK * 2)     // 16 KB
#define BUFB (ABYTES + BBYTES)     // 32 KB
#define GSTAGES 3
#define GSMEM_TOTAL (GSTAGES * BUFB)   // 96 KB
#define G_GM 8

__global__ __launch_bounds__(256, 2) void gemm_mma(
    const __nv_bfloat16* __restrict__ A,
    const __nv_bfloat16* __restrict__ Bt,
    const float* __restrict__ bias,
    float* __restrict__ C,
    int M, int Nt, int mt, int nt)
{
    extern __shared__ char smem[];
    const uint32_t sbase = smem_u32(smem);
    const int tid = threadIdx.x;
    const int wid = tid >> 5, lane = tid & 31;
    const int wm = wid >> 2, wn = wid & 3;     // 2 x 4 warp grid

    int bid = blockIdx.x;
    int per_group = G_GM * nt;
    int gid = bid / per_group;
    int first_m = gid * G_GM;
    int gsz = min(G_GM, mt - first_m);
    int rem = bid % per_group;
    const int m0 = (first_m + rem % gsz) * GBM;
    const int n0 = (rem / gsz) * GBN;

    float acc[4][4][4];
    #pragma unroll
    for (int i = 0; i < 4; i++)
        #pragma unroll
        for (int j = 0; j < 4; j++)
            #pragma unroll
            for (int r = 0; r < 4; r++) acc[i][j][r] = 0.f;

    auto load_tile = [&](int it, int buf) {
        const int k0 = it * GBK;
        const uint32_t sA = sbase + buf * BUFB;
        const uint32_t sB = sA + ABYTES;
        #pragma unroll
        for (int p = 0; p < 4; p++) {
            int id = p * 256 + tid;
            int row = id >> 3, ch = id & 7;
            uint32_t so = swz128((uint32_t)(row * 128 + ch * 16));
            int m = min(m0 + row, M - 1);
            cp16(sA + so, A  + (size_t)m * Kp + k0 + ch * 8);
            cp16(sB + so, Bt + (size_t)(n0 + row) * Kp + k0 + ch * 8);
        }
        CP_COMMIT();
    };

    auto compute = [&](int buf) {
        const uint32_t sA = sbase + buf * BUFB + (uint32_t)(wm * 64 * 128);
        const uint32_t sB = sbase + buf * BUFB + ABYTES + (uint32_t)(wn * 32 * 128);
        #pragma unroll
        for (int kk = 0; kk < 4; kk++) {
            uint32_t afr[4][4];
            #pragma unroll
            for (int mi = 0; mi < 4; mi++) {
                int row = mi * 16 + (lane & 15);
                int cb = kk * 32 + ((lane >> 4) << 4);
                LDSM_X4(afr[mi], sA + swz128((uint32_t)(row * 128 + cb)));
            }
            uint32_t bfr[4][2];
            #pragma unroll
            for (int bj = 0; bj < 2; bj++) {
                int row = bj * 16 + ((lane >> 4) << 3) + (lane & 7);
                int cb = kk * 32 + (((lane >> 3) & 1) << 4);
                uint32_t r[4];
                LDSM_X4(r, sB + swz128((uint32_t)(row * 128 + cb)));
                bfr[2 * bj][0] = r[0];     bfr[2 * bj][1] = r[1];
                bfr[2 * bj + 1][0] = r[2]; bfr[2 * bj + 1][1] = r[3];
            }
            #pragma unroll
            for (int mi = 0; mi < 4; mi++)
                #pragma unroll
                for (int nj = 0; nj < 4; nj++)
                    MMA16816(acc[mi][nj], afr[mi], bfr[nj]);
        }
    };

    load_tile(0, 0);
    load_tile(1, 1);
    for (int it = 0; it < GNIT; it++) {
        if (it + 1 < GNIT)
            asm volatile("cp.async.wait_group 1;" ::: "memory");
        else
            asm volatile("cp.async.wait_group 0;" ::: "memory");
        __syncthreads();
        if (it + 2 < GNIT) load_tile(it + 2, (it + 2) % GSTAGES);
        compute(it % GSTAGES);
    }

    const int mbase = m0 + wm * 64;
    const int nbase = n0 + wn * 32;
    #pragma unroll
    for (int mi = 0; mi < 4; mi++) {
        #pragma unroll
        for (int nj = 0; nj < 4; nj++) {
            int r0 = mbase + mi * 16 + (lane >> 2);
            int c = nbase + nj * 8 + 2 * (lane & 3);
            float bx = bias[c], by = bias[c + 1];
            if (r0 < M) {
                float2 o = make_float2(acc[mi][nj][0] + bx, acc[mi][nj][1] + by);
                *(float2*)(C + (size_t)r0 * Nt + c) = o;
            }
            if (r0 + 8 < M) {
                float2 o = make_float2(acc[mi][nj][2] + bx, acc[mi][nj][3] + by);
                *(float2*)(C + (size_t)(r0 + 8) * Nt + c) = o;
            }
        }
    }
}

// ===========================================================================
// RMSNorm in-place over q / k slices of g_qkv.
// ===========================================================================
__global__ __launch_bounds__(256) void rmsnorm_kernel(
    float* __restrict__ qkv, const float* __restrict__ qw,
    const float* __restrict__ kw)
{
    const int row = blockIdx.x;
    const int which = blockIdx.y;
    const float* w = which ? kw : qw;
    float* p = qkv + (size_t)row * QKV_N + which * Cq;

    float ss = 0.f;
    for (int c = threadIdx.x * 4; c < Cq; c += 256 * 4) {
        float4 v = *(const float4*)(p + c);
        ss += v.x * v.x + v.y * v.y + v.z * v.z + v.w * v.w;
    }
    #pragma unroll
    for (int o = 16; o; o >>= 1) ss += __shfl_xor_sync(0xffffffffu, ss, o);
    __shared__ float red[8];
    if ((threadIdx.x & 31) == 0) red[threadIdx.x >> 5] = ss;
    __syncthreads();
    if (threadIdx.x < 8) {
        float v = red[threadIdx.x];
        #pragma unroll
        for (int o = 4; o; o >>= 1) v += __shfl_xor_sync(0xffu, v, o);
        if (threadIdx.x == 0) red[0] = v;
    }
    __syncthreads();
    const float inv = rsqrtf(red[0] * (1.f / Cq) + EPSq);
    for (int c = threadIdx.x * 4; c < Cq; c += 256 * 4) {
        float4 v = *(const float4*)(p + c);
        float4 wv = *(const float4*)(w + c);
        v.x *= inv * wv.x; v.y *= inv * wv.y;
        v.z *= inv * wv.z; v.w *= inv * wv.w;
        *(float4*)(p + c) = v;
    }
}

// ===========================================================================
// Flash attention with bf16 mma.sync + hi/lo splits.
// Block = (q_tile 64, head, batch). 256 threads, 8 warps.
// Warp grid 4x2: S warp tile 16x32, O warp tile 16x64.
// Smem strides chosen so (stride*2) % 128 == 16 -> conflict-free ldmatrix.
// Epilogue writes tripled bf16 layout [hi|hi|lo] directly to g_as.
// ===========================================================================
#define FQK_S 264              // elements per row: [hi 128 | lo 128] + 8 pad
#define FQK_B (FQK_S * 2)      // 528 bytes
#define FV_S 264               // [vh 128 | vl 128] + 8
#define FV_B (FV_S * 2)
#define FPS_S 68               // fp32 S row stride
#define FPB_S 136              // bf16 P row: [ph 64 | pl 64] + 8
#define FPB_B (FPB_S * 2)      // 272 bytes

#define FA_Q_OFF 0
#define FA_K_OFF (64 * FQK_S * 2)                 // 33792
#define FA_V_OFF (FA_K_OFF + 64 * FQK_S * 2)      // 67584
#define FA_PS_OFF (FA_V_OFF + 64 * FV_S * 2)      // 101376
#define FA_PB_OFF (FA_PS_OFF + 64 * FPS_S * 4)    // 118784
#define FA_ML_OFF (FA_PB_OFF + 64 * FPB_S * 2)    // 136192
#define FA_SMEM_BYTES (FA_ML_OFF + 3 * 64 * 4)    // 136960

__global__ __launch_bounds__(256, 1) void flash_attn_mma(
    const float* __restrict__ qkv, __nv_bfloat16* __restrict__ outAs)
{
    extern __shared__ char sm[];
    __nv_bfloat16* Qs = (__nv_bfloat16*)(sm + FA_Q_OFF);
    __nv_bfloat16* Ks = (__nv_bfloat16*)(sm + FA_K_OFF);
    __nv_bfloat16* Vs = (__nv_bfloat16*)(sm + FA_V_OFF);
    float*         Ps = (float*)(sm + FA_PS_OFF);
    __nv_bfloat16* Pb = (__nv_bfloat16*)(sm + FA_PB_OFF);
    float*        m_s = (float*)(sm + FA_ML_OFF);
    float*        l_s = m_s + 64;
    float*       corr = l_s + 64;

    const uint32_t sq  = smem_u32(Qs);
    const uint32_t skm = smem_u32(Ks);
    const uint32_t svm = smem_u32(Vs);
    const uint32_t spb = smem_u32(Pb);

    const int qt = blockIdx.x;
    const int h  = blockIdx.y;
    const int b  = blockIdx.z;
    const int tid = threadIdx.x;
    const int wid = tid >> 5, lane = tid & 31;
    const int wm = wid >> 1, wn = wid & 1;          // 4 x 2 warp grid
    const float scale = 0.08838834764831845f;       // 128^-0.5

    const int q0 = qt * 64;
    const float* qbase = qkv + (size_t)b * Nq * QKV_N + h * Dq;
    const float* kbase = qbase + Cq;
    const float* vbase = qbase + 2 * Cq;

    // ---- load Q tile, prescale, split hi/lo ----
    for (int idx = tid; idx < 64 * 32; idx += 256) {
        int r = idx >> 5, c4 = (idx & 31) * 4;
        int n = q0 + r;
        float4 v = make_float4(0.f, 0.f, 0.f, 0.f);
        if (n < Nq) v = *(const float4*)(qbase + (size_t)n * QKV_N + c4);
        float f[4] = {v.x * scale, v.y * scale, v.z * scale, v.w * scale};
        #pragma unroll
        for (int j = 0; j < 4; j++) {
            __nv_bfloat16 hh = __float2bfloat16_rn(f[j]);
            __nv_bfloat16 ll = __float2bfloat16_rn(f[j] - __bfloat162float(hh));
            Qs[r * FQK_S + c4 + j] = hh;
            Qs[r * FQK_S + 128 + c4 + j] = ll;
        }
    }
    if (tid < 64) { m_s[tid] = -1e30f; l_s[tid] = 0.f; }

    float acc_o[8][4];
    #pragma unroll
    for (int nj = 0; nj < 8; nj++)
        #pragma unroll
        for (int r = 0; r < 4; r++) acc_o[nj][r] = 0.f;
    __syncthreads();

    for (int kt = 0; kt < 17; kt++) {
        const int k0g = kt * 64;

        // ---- load K, V tiles, split hi/lo ----
        for (int idx = tid; idx < 64 * 32; idx += 256) {
            int r = idx >> 5, c4 = (idx & 31) * 4;
            int n = k0g + r;
            float4 kv = make_float4(0.f, 0.f, 0.f, 0.f);
            float4 vv = make_float4(0.f, 0.f, 0.f, 0.f);
            if (n < Nq) {
                kv = *(const float4*)(kbase + (size_t)n * QKV_N + c4);
                vv = *(const float4*)(vbase + (size_t)n * QKV_N + c4);
            }
            float kf[4] = {kv.x, kv.y, kv.z, kv.w};
            float vf[4] = {vv.x, vv.y, vv.z, vv.w};
            #pragma unroll
            for (int j = 0; j < 4; j++) {
                __nv_bfloat16 khh = __float2bfloat16_rn(kf[j]);
                __nv_bfloat16 kll = __float2bfloat16_rn(kf[j] - __bfloat162float(khh));
                Ks[r * FQK_S + c4 + j] = khh;
                Ks[r * FQK_S + 128 + c4 + j] = kll;
                __nv_bfloat16 vhh = __float2bfloat16_rn(vf[j]);
                __nv_bfloat16 vll = __float2bfloat16_rn(vf[j] - __bfloat162float(vhh));
                Vs[r * FV_S + c4 + j] = vhh;
                Vs[r * FV_S + 128 + c4 + j] = vll;
            }
        }
        __syncthreads();

        // ---- S = Q K^T via 3-term bf16 (24 k16-steps) ----
        float accs[4][4];
        #pragma unroll
        for (int nj = 0; nj < 4; nj++)
            #pragma unroll
            for (int r = 0; r < 4; r++) accs[nj][r] = 0.f;

        #pragma unroll
        for (int ks = 0; ks < 24; ks++) {
            int aoff, boff;
            if (ks < 8)       { aoff = ks * 32;             boff = ks * 32; }
            else if (ks < 16) { aoff = 256 + (ks - 8) * 32; boff = (ks - 8) * 32; }
            else              { aoff = (ks - 16) * 32;      boff = 256 + (ks - 16) * 32; }

            uint32_t afr[4];
            {
                int row = wm * 16 + (lane & 15);
                LDSM_X4(afr, sq + (uint32_t)(row * FQK_B + aoff + ((lane >> 4) << 4)));
            }
            uint32_t bfr[4][2];
            #pragma unroll
            for (int bj = 0; bj < 2; bj++) {
                int row = wn * 32 + bj * 16 + ((lane >> 4) << 3) + (lane & 7);
                uint32_t r[4];
                LDSM_X4(r, skm + (uint32_t)(row * FQK_B + boff + (((lane >> 3) & 1) << 4)));
                bfr[2 * bj][0] = r[0];     bfr[2 * bj][1] = r[1];
                bfr[2 * bj + 1][0] = r[2]; bfr[2 * bj + 1][1] = r[3];
            }
            #pragma unroll
            for (int nj = 0; nj < 4; nj++)
                MMA16816(accs[nj], afr, bfr[nj]);
        }

        // ---- write S fragments to Ps ----
        {
            int r0 = wm * 16 + (lane >> 2);
            int cb = wn * 32 + 2 * (lane & 3);
            #pragma unroll
            for (int nj = 0; nj < 4; nj++) {
                int c = cb + nj * 8;
                Ps[r0 * FPS_S + c]           = accs[nj][0];
                Ps[r0 * FPS_S + c + 1]       = accs[nj][1];
                Ps[(r0 + 8) * FPS_S + c]     = accs[nj][2];
                Ps[(r0 + 8) * FPS_S + c + 1] = accs[nj][3];
            }
        }
        __syncthreads();

        // ---- online softmax (4 threads per row), write ph/pl ----
        {
            const int r = tid >> 2;
            const int q4 = tid & 3;
            float mx = -1e30f;
            #pragma unroll
            for (int c = q4 * 16; c < q4 * 16 + 16; c++) {
                bool valid = (k0g + c < Nq);
                float sv = valid ? Ps[r * FPS_S + c] : -1e30f;
                mx = fmaxf(mx, sv);
            }
            mx = fmaxf(mx, __shfl_xor_sync(0xffffffffu, mx, 1));
            mx = fmaxf(mx, __shfl_xor_sync(0xffffffffu, mx, 2));
            const float mold = m_s[r];
            const float mnew = fmaxf(mold, mx);
            float sum = 0.f;
            #pragma unroll
            for (int c = q4 * 16; c < q4 * 16 + 16; c++) {
                bool valid = (k0g + c < Nq);
                float pv = valid ? __expf(Ps[r * FPS_S + c] - mnew) : 0.f;
                sum += pv;
                __nv_bfloat16 ph = __float2bfloat16_rn(pv);
                __nv_bfloat16 pl = __float2bfloat16_rn(pv - __bfloat162float(ph));
                Pb[r * FPB_S + c]      = ph;
                Pb[r * FPB_S + 64 + c] = pl;
            }
            sum += __shfl_xor_sync(0xffffffffu, sum, 1);
            sum += __shfl_xor_sync(0xffffffffu, sum, 2);
            if (q4 == 0) {
                float cr = __expf(mold - mnew);
                l_s[r] = l_s[r] * cr + sum;
                m_s[r] = mnew;
                corr[r] = cr;
            }
        }
        __syncthreads();

        // ---- rescale O accumulators ----
        {
            float c0 = corr[wm * 16 + (lane >> 2)];
            float c1 = corr[wm * 16 + (lane >> 2) + 8];
            #pragma unroll
            for (int nj = 0; nj < 8; nj++) {
                acc_o[nj][0] *= c0; acc_o[nj][1] *= c0;
                acc_o[nj][2] *= c1; acc_o[nj][3] *= c1;
            }
        }

        // ---- O += P' V' via 3-term bf16 (12 k16-steps over 64 keys) ----
        #pragma unroll
        for (int ks = 0; ks < 12; ks++) {
            int aoff = (ks < 4) ? ks * 32
                     : (ks < 8) ? 128 + (ks - 4) * 32
                                : (ks - 8) * 32;
            int vco  = (ks < 8) ? 0 : 256;
            int krow = (ks & 3) * 16;

            uint32_t afr[4];
            {
                int row = wm * 16 + (lane & 15);
                LDSM_X4(afr, spb + (uint32_t)(row * FPB_B + aoff + ((lane >> 4) << 4)));
            }
            uint32_t bfr[8][2];
            #pragma unroll
            for (int g = 0; g < 4; g++) {
                int vrow = krow + (lane & 7) + (((lane >> 3) & 1) << 3);
                int bcol = vco + (wn * 64 + g * 16) * 2 + ((lane >> 4) << 4);
                uint32_t r[4];
                LDSM_X4_T(r, svm + (uint32_t)(vrow * FV_B + bcol));
                bfr[2 * g][0] = r[0];     bfr[2 * g][1] = r[1];
                bfr[2 * g + 1][0] = r[2]; bfr[2 * g + 1][1] = r[3];
            }
            #pragma unroll
            for (int nj = 0; nj < 8; nj++)
                MMA16816(acc_o[nj], afr, bfr[nj]);
        }
        __syncthreads();
    }

    // ---- epilogue: normalize, split hi/lo, write tripled layout to g_as ----
    {
        int r0 = wm * 16 + (lane >> 2);
        float invl0 = 1.f / l_s[r0];
        float invl1 = 1.f / l_s[r0 + 8];
        int n0v = q0 + r0;
        int n1v = q0 + r0 + 8;
        #pragma unroll
        for (int nj = 0; nj < 8; nj++) {
            int c = h * Dq + wn * 64 + nj * 8 + 2 * (lane & 3);
            if (n0v < Nq) {
                float o0 = acc_o[nj][0] * invl0;
                float o1 = acc_o[nj][1] * invl0;
                __nv_bfloat16 h0 = __float2bfloat16_rn(o0);
                __nv_bfloat16 h1 = __float2bfloat16_rn(o1);
                __nv_bfloat16 l0 = __float2bfloat16_rn(o0 - __bfloat162float(h0));
                __nv_bfloat16 l1 = __float2bfloat16_rn(o1 - __bfloat162float(h1));
                __nv_bfloat162 hh; hh.x = h0; hh.y = h1;
                __nv_bfloat162 ll; ll.x = l0; ll.y = l1;
                __nv_bfloat16* row = outAs + (size_t)(b * Nq + n0v) * Kp;
                *(__nv_bfloat162*)(row + c)          = hh;
                *(__nv_bfloat162*)(row + Cq + c)     = hh;
                *(__nv_bfloat162*)(row + 2 * Cq + c) = ll;
            }
            if (n1v < Nq) {
                float o0 = acc_o[nj][2] * invl1;
                float o1 = acc_o[nj][3] * invl1;
                __nv_bfloat16 h0 = __float2bfloat16_rn(o0);
                __nv_bfloat16 h1 = __float2bfloat16_rn(o1);
                __nv_bfloat16 l0 = __float2bfloat16_rn(o0 - __bfloat162float(h0));
                __nv_bfloat16 l1 = __float2bfloat16_rn(o1 - __bfloat162float(h1));
                __nv_bfloat162 hh; hh.x = h0; hh.y = h1;
                __nv_bfloat162 ll; ll.x = l0; ll.y = l1;
                __nv_bfloat16* row = outAs + (size_t)(b * Nq + n1v) * Kp;
                *(__nv_bfloat162*)(row + c)          = hh;
                *(__nv_bfloat162*)(row + Cq + c)     = hh;
                *(__nv_bfloat162*)(row + 2 * Cq + c) = ll;
            }
        }
    }
}

// ===========================================================================
extern "C" void kernel_launch(void* const* d_in, const int* in_sizes, int n_in,
                              void* d_out, int out_size)
{
    const float* x        = (const float*)d_in[0];
    const float* qkv_w    = (const float*)d_in[1];
    const float* qkv_b    = (const float*)d_in[2];
    const float* q_norm_w = (const float*)d_in[3];
    const float* k_norm_w = (const float*)d_in[4];
    const float* proj_w   = (const float*)d_in[5];
    const float* proj_b   = (const float*)d_in[6];
    float* out = (float*)d_out;

    float* qkvp = nullptr;
    __nv_bfloat16 *asp = nullptr, *wqp = nullptr, *wpp = nullptr;
    cudaGetSymbolAddress((void**)&qkvp, g_qkv);
    cudaGetSymbolAddress((void**)&asp, g_as);
    cudaGetSymbolAddress((void**)&wqp, g_wq);
    cudaGetSymbolAddress((void**)&wpp, g_wp);

    cudaFuncSetAttribute(gemm_mma,
                         cudaFuncAttributeMaxDynamicSharedMemorySize, GSMEM_TOTAL);
    cudaFuncSetAttribute(flash_attn_mma,
                         cudaFuncAttributeMaxDynamicSharedMemorySize, FA_SMEM_BYTES);

    const int mt = (Mq + GBM - 1) / GBM;        // 65
    const int nt_qkv = QKV_N / GBN;             // 75
    const int nt_prj = Cq / GBN;                // 25

    // 1) split inputs / weights into bf16 hi/lo (K tripled)
    {
        size_t e2 = (size_t)Mq * Cq / 2;
        split_a_kernel<<<(unsigned)((e2 + 255) / 256), 256>>>(x, asp, Mq);
    }
    split_wt_kernel<<<dim3(QKV_N / 32, Cq / 32), dim3(32, 8)>>>(qkv_w, wqp, QKV_N);
    split_wt_kernel<<<dim3(Cq / 32, Cq / 32), dim3(32, 8)>>>(proj_w, wpp, Cq);

    // 2) qkv = x @ qkv_w + b
    gemm_mma<<<mt * nt_qkv, 256, GSMEM_TOTAL>>>(
        asp, wqp, qkv_b, qkvp, Mq, QKV_N, mt, nt_qkv);

    // 3) RMSNorm q/k in place
    rmsnorm_kernel<<<dim3(Mq, 2), 256>>>(qkvp, q_norm_w, k_norm_w);

    // 4) attention -> g_as (tripled bf16 layout, ready for proj GEMM)
    flash_attn_mma<<<dim3(17, Hq, Bq), 256, FA_SMEM_BYTES>>>(qkvp, asp);

    // 5) out = att @ proj_w + b
    gemm_mma<<<mt * nt_prj, 256, GSMEM_TOTAL>>>(
        asp, wpp, proj_b, out, Mq, Cq, mt, nt_prj);
}